// round 4
// baseline (speedup 1.0000x reference)
#include <cuda_runtime.h>
#include <math_constants.h>

#define EPS_WH 1e-07f
#define MAX_WH 10000000.0f
#define THREADS 256

// Per-batch partial losses (B = 1024 in this problem; padded for safety).
__device__ float g_partial[4096];
__device__ int   g_count;   // zero-initialized; reset by last block each run

__device__ __forceinline__ float clip_wh(float v) {
    return fminf(fmaxf(v, EPS_WH), MAX_WH);
}

// Map float bits to a monotonically ordered uint32 (standard sortable trick).
__device__ __forceinline__ unsigned int f2sortable(float f) {
    unsigned int u = __float_as_uint(f);
    return (u & 0x80000000u) ? ~u : (u | 0x80000000u);
}

// One block per batch element: argmax over HW heatmap values, gather 4 floats,
// closed-form GWD loss. Last block to finish performs the deterministic mean.
__global__ void __launch_bounds__(THREADS)
gwd_fused_kernel(const float* __restrict__ hm,
                 const float* __restrict__ ab,
                 const float* __restrict__ trig,
                 const float* __restrict__ center,
                 const float* __restrict__ target,
                 float* __restrict__ out,
                 int HW, int B)
{
    const int b = blockIdx.x;
    const int t = threadIdx.x;

    // ---- argmax over hm[b, 0, :] (sigmoid is monotone -> same argmax) ----
    const float4* hm4 = reinterpret_cast<const float4*>(hm + (size_t)b * HW);
    const int n4 = HW >> 2;

    float best = -CUDART_INF_F;
    int bidx = 0;
    #pragma unroll 4
    for (int i = t; i < n4; i += THREADS) {
        float4 v = hm4[i];
        int base = i << 2;
        if (v.x > best) { best = v.x; bidx = base; }
        if (v.y > best) { best = v.y; bidx = base + 1; }
        if (v.z > best) { best = v.z; bidx = base + 2; }
        if (v.w > best) { best = v.w; bidx = base + 3; }
    }

    // Pack (sortable value | ~idx): max over this picks max value, and on
    // value ties the smallest index (matching jnp.argmax first-occurrence).
    unsigned long long key =
        ((unsigned long long)f2sortable(best) << 32) |
        (unsigned long long)(unsigned int)(~bidx);

    // warp reduce
    #pragma unroll
    for (int off = 16; off > 0; off >>= 1) {
        unsigned long long o = __shfl_xor_sync(0xffffffffu, key, off);
        key = (o > key) ? o : key;
    }

    __shared__ unsigned long long skey[THREADS / 32];
    if ((t & 31) == 0) skey[t >> 5] = key;
    __syncthreads();
    if (t < 32) {
        unsigned long long k = (t < THREADS / 32) ? skey[t] : 0ull;
        #pragma unroll
        for (int off = 16; off > 0; off >>= 1) {
            unsigned long long o = __shfl_xor_sync(0xffffffffu, k, off);
            k = (o > k) ? o : k;
        }
        if (t == 0) skey[0] = k;
    }
    __syncthreads();

    if (t == 0) {
        const int idx = (int)(~((unsigned int)(skey[0] & 0xffffffffu)));

        // ---- gather (4 scattered loads instead of streaming 268 MB) ----
        const float* abb = ab   + (size_t)b * 2 * HW;
        const float* tgb = trig + (size_t)b * 2 * HW;
        float a1    = abb[idx];
        float a2    = abb[HW + idx];
        float sin2A = tgb[idx];
        float cos2A = tgb[HW + idx];

        // pred box: deg roundtrip in the reference is identity, keep radians
        float r_p = 0.5f * atan2f(sin2A, cos2A);
        float xp = center[2 * b], yp = center[2 * b + 1];
        float wp = clip_wh(2.0f * a1);
        float hp = clip_wh(2.0f * a2);
        float s1p = 0.5f * wp, s2p = 0.5f * hp;
        float cp = cosf(r_p), sp = sinf(r_p);

        // target box
        float xt = target[5 * b + 0];
        float yt = target[5 * b + 1];
        float wt = clip_wh(target[5 * b + 2]);
        float ht = clip_wh(target[5 * b + 3]);
        float r_t = target[5 * b + 4] * (CUDART_PI_F / 180.0f);
        float s1t = 0.5f * wt, s2t = 0.5f * ht;
        float ct = cosf(r_t), st = sinf(r_t);

        float dx = xp - xt, dy = yp - yt;
        float xy_dist = dx * dx + dy * dy;

        // Sigma = R diag(s^2) R^T for 2x2: closed form
        float sp1_2 = s1p * s1p, sp2_2 = s2p * s2p;
        float st1_2 = s1t * s1t, st2_2 = s2t * s2t;

        float Ap = sp1_2 * cp * cp + sp2_2 * sp * sp;
        float Bp = sp1_2 * sp * sp + sp2_2 * cp * cp;
        float Cp = (sp1_2 - sp2_2) * cp * sp;

        float At = st1_2 * ct * ct + st2_2 * st * st;
        float Bt = st1_2 * st * st + st2_2 * ct * ct;
        float Ct = (st1_2 - st2_2) * ct * st;

        float tr_pt = Ap * At + Bp * Bt + 2.0f * Cp * Ct;
        float det_sqrt = sqrtf(fmaxf(s1p * s2p * s1t * s2t, 0.0f));

        float whr = sp1_2 + sp2_2 + st1_2 + st2_2
                  - 2.0f * sqrtf(fmaxf(tr_pt + 2.0f * det_sqrt, 0.0f));

        float dist = fmaxf(xy_dist + whr, 0.0f);
        float loss = 1.0f - 1.0f / (1.0f + dist);
        g_partial[b] = loss;
    }
    __syncthreads();

    // ---- last-block-done: deterministic mean over all partials ----
    __shared__ bool amLast;
    if (t == 0) {
        __threadfence();
        amLast = (atomicAdd(&g_count, 1) == gridDim.x - 1);
    }
    __syncthreads();

    if (amLast) {
        float acc = 0.0f;
        // Fixed order per thread, single block: bitwise deterministic.
        for (int i = t; i < B; i += THREADS) acc += g_partial[i];

        __shared__ float sh[THREADS];
        sh[t] = acc;
        __syncthreads();
        #pragma unroll
        for (int s = THREADS / 2; s > 0; s >>= 1) {
            if (t < s) sh[t] += sh[t + s];
            __syncthreads();
        }
        if (t == 0) {
            out[0] = sh[0] / (float)B;
            g_count = 0;  // reset for next graph replay
        }
    }
}

extern "C" void kernel_launch(void* const* d_in, const int* in_sizes, int n_in,
                              void* d_out, int out_size)
{
    const float* hm     = (const float*)d_in[0];  // (B,1,H,W)
    const float* ab     = (const float*)d_in[1];  // (B,2,H,W)
    const float* trig   = (const float*)d_in[2];  // (B,2,H,W)
    const float* center = (const float*)d_in[3];  // (B,2)
    const float* target = (const float*)d_in[4];  // (B,5)
    float* out = (float*)d_out;

    const int B  = in_sizes[4] / 5;
    const int HW = in_sizes[0] / B;

    gwd_fused_kernel<<<B, THREADS>>>(hm, ab, trig, center, target, out, HW, B);
}

// round 5
// speedup vs baseline: 1.0025x; 1.0025x over previous
#include <cuda_runtime.h>
#include <math_constants.h>

#define EPS_WH 1e-07f
#define MAX_WH 10000000.0f
#define THREADS 256

// Per-batch partial losses (B = 1024 in this problem; padded for safety).
__device__ float g_partial[4096];
__device__ int   g_count;   // zero-initialized; reset by last block each run

__device__ __forceinline__ float clip_wh(float v) {
    return fminf(fmaxf(v, EPS_WH), MAX_WH);
}

// Map float bits to a monotonically ordered uint32 (standard sortable trick).
__device__ __forceinline__ unsigned int f2sortable(float f) {
    unsigned int u = __float_as_uint(f);
    return (u & 0x80000000u) ? ~u : (u | 0x80000000u);
}

// One block per batch element: branchless argmax over HW heatmap values,
// gather 4 floats, closed-form GWD loss. Last block does the deterministic mean.
__global__ void __launch_bounds__(THREADS)
gwd_fused_kernel(const float* __restrict__ hm,
                 const float* __restrict__ ab,
                 const float* __restrict__ trig,
                 const float* __restrict__ center,
                 const float* __restrict__ target,
                 float* __restrict__ out,
                 int HW, int B)
{
    const int b = blockIdx.x;
    const int t = threadIdx.x;

    // ---- argmax over hm[b, 0, :] (sigmoid is monotone -> same argmax) ----
    const float4* hm4 = reinterpret_cast<const float4*>(hm + (size_t)b * HW);
    const int n4 = HW >> 2;

    float best = -CUDART_INF_F;
    int bidx = 0;

    // Branchless: per float4, FMNMX tree for lane max, SEL chain for the
    // first-occurrence intra-quad index, one FMNMX + one SEL carried chain.
    #pragma unroll 8
    for (int i = t; i < n4; i += THREADS) {
        float4 v = hm4[i];
        int base = i << 2;

        float m = fmaxf(fmaxf(v.x, v.y), fmaxf(v.z, v.w));

        int idx4 = (v.z == m) ? (base + 2) : (base + 3);
        idx4     = (v.y == m) ? (base + 1) : idx4;
        idx4     = (v.x == m) ?  base      : idx4;

        bidx = (m > best) ? idx4 : bidx;   // strict > keeps earliest i on ties
        best = fmaxf(best, m);
    }

    // Pack (sortable value | ~idx): max over this picks max value, and on
    // value ties the smallest index (matching jnp.argmax first-occurrence).
    unsigned long long key =
        ((unsigned long long)f2sortable(best) << 32) |
        (unsigned long long)(unsigned int)(~bidx);

    // warp reduce
    #pragma unroll
    for (int off = 16; off > 0; off >>= 1) {
        unsigned long long o = __shfl_xor_sync(0xffffffffu, key, off);
        key = (o > key) ? o : key;
    }

    __shared__ unsigned long long skey[THREADS / 32];
    if ((t & 31) == 0) skey[t >> 5] = key;
    __syncthreads();
    if (t < 32) {
        unsigned long long k = (t < THREADS / 32) ? skey[t] : 0ull;
        #pragma unroll
        for (int off = 16; off > 0; off >>= 1) {
            unsigned long long o = __shfl_xor_sync(0xffffffffu, k, off);
            k = (o > k) ? o : k;
        }
        if (t == 0) skey[0] = k;
    }
    __syncthreads();

    if (t == 0) {
        const int idx = (int)(~((unsigned int)(skey[0] & 0xffffffffu)));

        // ---- gather (4 scattered loads instead of streaming 268 MB) ----
        const float* abb = ab   + (size_t)b * 2 * HW;
        const float* tgb = trig + (size_t)b * 2 * HW;
        float a1    = abb[idx];
        float a2    = abb[HW + idx];
        float sin2A = tgb[idx];
        float cos2A = tgb[HW + idx];

        // pred box: deg roundtrip in the reference is identity, keep radians
        float r_p = 0.5f * atan2f(sin2A, cos2A);
        float xp = center[2 * b], yp = center[2 * b + 1];
        float wp = clip_wh(2.0f * a1);
        float hp = clip_wh(2.0f * a2);
        float s1p = 0.5f * wp, s2p = 0.5f * hp;
        float cp = cosf(r_p), sp = sinf(r_p);

        // target box
        float xt = target[5 * b + 0];
        float yt = target[5 * b + 1];
        float wt = clip_wh(target[5 * b + 2]);
        float ht = clip_wh(target[5 * b + 3]);
        float r_t = target[5 * b + 4] * (CUDART_PI_F / 180.0f);
        float s1t = 0.5f * wt, s2t = 0.5f * ht;
        float ct = cosf(r_t), st = sinf(r_t);

        float dx = xp - xt, dy = yp - yt;
        float xy_dist = dx * dx + dy * dy;

        // Sigma = R diag(s^2) R^T for 2x2: closed form
        float sp1_2 = s1p * s1p, sp2_2 = s2p * s2p;
        float st1_2 = s1t * s1t, st2_2 = s2t * s2t;

        float Ap = sp1_2 * cp * cp + sp2_2 * sp * sp;
        float Bp = sp1_2 * sp * sp + sp2_2 * cp * cp;
        float Cp = (sp1_2 - sp2_2) * cp * sp;

        float At = st1_2 * ct * ct + st2_2 * st * st;
        float Bt = st1_2 * st * st + st2_2 * ct * ct;
        float Ct = (st1_2 - st2_2) * ct * st;

        float tr_pt = Ap * At + Bp * Bt + 2.0f * Cp * Ct;
        float det_sqrt = sqrtf(fmaxf(s1p * s2p * s1t * s2t, 0.0f));

        float whr = sp1_2 + sp2_2 + st1_2 + st2_2
                  - 2.0f * sqrtf(fmaxf(tr_pt + 2.0f * det_sqrt, 0.0f));

        float dist = fmaxf(xy_dist + whr, 0.0f);
        float loss = 1.0f - 1.0f / (1.0f + dist);
        g_partial[b] = loss;
    }
    __syncthreads();

    // ---- last-block-done: deterministic mean over all partials ----
    __shared__ bool amLast;
    if (t == 0) {
        __threadfence();
        amLast = (atomicAdd(&g_count, 1) == gridDim.x - 1);
    }
    __syncthreads();

    if (amLast) {
        float acc = 0.0f;
        // Fixed order per thread, single block: bitwise deterministic.
        // __ldcg: bypass L1 (partials were written by other SMs).
        for (int i = t; i < B; i += THREADS) acc += __ldcg(&g_partial[i]);

        __shared__ float sh[THREADS];
        sh[t] = acc;
        __syncthreads();
        #pragma unroll
        for (int s = THREADS / 2; s > 0; s >>= 1) {
            if (t < s) sh[t] += sh[t + s];
            __syncthreads();
        }
        if (t == 0) {
            out[0] = sh[0] / (float)B;
            g_count = 0;  // reset for next graph replay
        }
    }
}

extern "C" void kernel_launch(void* const* d_in, const int* in_sizes, int n_in,
                              void* d_out, int out_size)
{
    const float* hm     = (const float*)d_in[0];  // (B,1,H,W)
    const float* ab     = (const float*)d_in[1];  // (B,2,H,W)
    const float* trig   = (const float*)d_in[2];  // (B,2,H,W)
    const float* center = (const float*)d_in[3];  // (B,2)
    const float* target = (const float*)d_in[4];  // (B,5)
    float* out = (float*)d_out;

    const int B  = in_sizes[4] / 5;
    const int HW = in_sizes[0] / B;

    gwd_fused_kernel<<<B, THREADS>>>(hm, ab, trig, center, target, out, HW, B);
}